// round 16
// baseline (speedup 1.0000x reference)
#include <cuda_runtime.h>
#include <cuda_fp16.h>
#include <cstdint>
#include <cstddef>

// Problem constants
constexpr int B_   = 128;
constexpr int NI   = 100;
constexpr int NS   = 50;
constexpr int OBJ  = 2048;
constexpr int SEM  = 300;
constexpr int SEMP = 304;
constexpr int PROJ = 1024;
constexpr int MI = B_ * NI;   // 12800
constexpr int MS = B_ * NS;   // 6400

// 128x128 GEMM pipeline (s_proj)
constexpr int NST = 3;
constexpr int STAGE_BYTES = 2 * 128 * 128;
constexpr int SMEM_DYN = NST * STAGE_BYTES;    // 96 KB

// 256x128 GEMM pipeline (sWT)
constexpr int NST2 = 4;
constexpr int STAGE2_BYTES = (256 + 128) * 128;
constexpr int SMEM_DYN2 = NST2 * STAGE2_BYTES; // 192 KB

// 128x256 wide GEMM pipeline (iproj / comb), 512 threads
constexpr int NSTW = 4;
constexpr int STAGEW_BYTES = (128 + 256) * 128;   // A 16KB + B 32KB
constexpr int SMEM_DYNW = NSTW * STAGEW_BYTES;    // 192 KB

// ---------------- scratch (device globals; no runtime allocation) ------------
__device__ __align__(16) __half g_att16[(size_t)B_ * 128 * 64];
__device__ __align__(16) __half g_sproj[(size_t)MS * PROJ];
__device__ __align__(16) __half g_sWT  [(size_t)OBJ * MS];
__device__ __align__(16) __half g_T    [(size_t)MI * OBJ];
__device__ __align__(16) __half g_iproj[(size_t)MI * PROJ];
__device__ __align__(16) __half g_i16  [(size_t)MI * OBJ];
__device__ __align__(16) __half g_s16  [(size_t)MS * SEMP];
__device__ __align__(16) __half g_vi16 [(size_t)PROJ * OBJ];
__device__ __align__(16) __half g_vs16 [(size_t)PROJ * SEMP];
__device__ __align__(16) __half g_vc16 [(size_t)OBJ * 2 * PROJ];
__device__ __align__(16) float  g_si[PROJ];
__device__ __align__(16) float  g_ss[PROJ];
__device__ __align__(16) float  g_sc[OBJ];

// ======================= helpers ==============================================
__device__ __forceinline__ uint32_t smem_u32(const void* p) {
    uint32_t a;
    asm("{ .reg .u64 t; cvta.to.shared.u64 t, %1; cvt.u32.u64 %0, t; }"
        : "=r"(a) : "l"(p));
    return a;
}

// ---------------- prep_i: fp16 convert of i only (low-reg, streaming) ---------
constexpr int PI_N4 = MI * OBJ / 4;

__global__ void prep_i_kernel(const float* __restrict__ i_in, __half* __restrict__ i16)
{
    for (int t = blockIdx.x * blockDim.x + threadIdx.x; t < PI_N4;
         t += gridDim.x * blockDim.x) {
        float4 v = reinterpret_cast<const float4*>(i_in)[t];
        __half2* d = reinterpret_cast<__half2*>(i16 + (size_t)t * 4);
        d[0] = __floats2half2_rn(v.x, v.y);
        d[1] = __floats2half2_rn(v.z, v.w);
    }
}

// ------- prep_s: convert s + vs to fp16 AND rownorm ss (gates sproj only) -----
constexpr int PS_NS  = MS * SEM / 4;
constexpr int PS_NVS = PROJ * SEM / 4;
constexpr int PS_TOT = PS_NS + PS_NVS;
constexpr int PS_CONV_BLOCKS = 1024;
constexpr int PS_BLOCKS = PS_CONV_BLOCKS + PROJ;

__global__ void prep_s_kernel(const float* __restrict__ s,  __half* __restrict__ s16,
                              const float* __restrict__ vs, __half* __restrict__ vs16,
                              const float* __restrict__ gs, float* __restrict__ ss)
{
    int blk = blockIdx.x;
    if (blk < PS_CONV_BLOCKS) {
        for (int t = blk * blockDim.x + threadIdx.x; t < PS_TOT;
             t += PS_CONV_BLOCKS * 256) {
            const float* src; __half* dst; int j = t;
            if (j < PS_NS) { src = s;  dst = s16; }
            else           { j -= PS_NS; src = vs; dst = vs16; }
            int row = j / 75, c = j % 75;
            float4 v = reinterpret_cast<const float4*>(src)[j];
            __half2* d = reinterpret_cast<__half2*>(dst + (size_t)row * SEMP + c * 4);
            d[0] = __floats2half2_rn(v.x, v.y);
            d[1] = __floats2half2_rn(v.z, v.w);
        }
        return;
    }
    int r = blk - PS_CONV_BLOCKS;
    float s2 = 0.f;
    for (int k = threadIdx.x; k < SEM; k += blockDim.x) {
        float x = vs[(size_t)r * SEM + k];
        s2 += x * x;
    }
    __shared__ float red[256];
    red[threadIdx.x] = s2;
    __syncthreads();
    #pragma unroll
    for (int o = 128; o > 0; o >>= 1) {
        if (threadIdx.x < o) red[threadIdx.x] += red[threadIdx.x + o];
        __syncthreads();
    }
    if (threadIdx.x == 0) ss[r] = gs[r] * rsqrtf(red[0]);
}

// ------- prep_vv: fp16 convert of vi + vc --------------------------------------
constexpr int PV_NVI = PROJ * OBJ / 4;
constexpr int PV_NVC = OBJ * 2 * PROJ / 4;
constexpr int PV_TOT = PV_NVI + PV_NVC;

__global__ void prep_vv_kernel(const float* __restrict__ vi, __half* __restrict__ vi16,
                               const float* __restrict__ vc, __half* __restrict__ vc16)
{
    for (int t = blockIdx.x * blockDim.x + threadIdx.x; t < PV_TOT;
         t += gridDim.x * blockDim.x) {
        const float* src; __half* dst; int j = t;
        if (j < PV_NVI) { src = vi; dst = vi16; }
        else            { j -= PV_NVI; src = vc; dst = vc16; }
        float4 v = reinterpret_cast<const float4*>(src)[j];
        __half2* d = reinterpret_cast<__half2*>(dst + (size_t)j * 4);
        d[0] = __floats2half2_rn(v.x, v.y);
        d[1] = __floats2half2_rn(v.z, v.w);
    }
}

// ------- prep2b: rownorm si + sc, attention softmax ---------------------------
constexpr int P2_SI = PROJ;
constexpr int P2_SC = OBJ;
constexpr int P2_ATT = B_ * 128 / 256;
constexpr int P2_BLOCKS = P2_SI + P2_SC + P2_ATT;

__global__ void prep2b_kernel(const float* __restrict__ vi, const float* __restrict__ gi,
                              float* __restrict__ si,
                              const float* __restrict__ vc, const float* __restrict__ gc,
                              float* __restrict__ sc,
                              const float* __restrict__ pi, const float* __restrict__ ps,
                              const int* __restrict__ mask_s, __half* __restrict__ att16)
{
    int blk = blockIdx.x;
    if (blk >= P2_SI + P2_SC) {
        int idx = (blk - P2_SI - P2_SC) * blockDim.x + threadIdx.x;
        int b = idx >> 7;
        int m = idx & 127;
        __half2* orow = reinterpret_cast<__half2*>(att16 + (size_t)idx * 64);
        if (m >= NI) {
            #pragma unroll
            for (int j = 0; j < 32; j++) orow[j] = __halves2half2(__half(0.f), __half(0.f));
            return;
        }
        int rix = b * NI + m;
        float px = pi[rix * 2 + 0];
        float py = pi[rix * 2 + 1];
        int mm = mask_s[b];
        const float* psb = ps + (size_t)b * NS * 2;

        float d[NS];
        float mx = -1e30f;
        #pragma unroll
        for (int j = 0; j < NS; j++) {
            float dx = px - psb[2 * j + 0];
            float dy = py - psb[2 * j + 1];
            d[j] = sqrtf(dx * dx + dy * dy);
            if (j < mm) mx = fmaxf(mx, d[j]);
        }
        float sum = 0.f;
        #pragma unroll
        for (int j = 0; j < NS; j++) {
            float e = (j < mm) ? __expf(d[j] - mx) : 0.f;
            d[j] = e;
            sum += e;
        }
        float inv = 1.f / sum;
        #pragma unroll
        for (int j = 0; j < 32; j++) {
            float lo = (2 * j     < NS) ? d[2 * j]     * inv : 0.f;
            float hi = (2 * j + 1 < NS) ? d[2 * j + 1] * inv : 0.f;
            orow[j] = __floats2half2_rn(lo, hi);
        }
        return;
    }
    const float *v, *g; float* out; int K, r;
    if (blk < P2_SI) { v = vi; g = gi; out = si; K = OBJ;      r = blk; }
    else             { v = vc; g = gc; out = sc; K = 2 * PROJ; r = blk - P2_SI; }

    float s = 0.f;
    for (int k = threadIdx.x; k < K; k += blockDim.x) {
        float x = v[(size_t)r * K + k];
        s += x * x;
    }
    __shared__ float red[256];
    red[threadIdx.x] = s;
    __syncthreads();
    #pragma unroll
    for (int o = 128; o > 0; o >>= 1) {
        if (threadIdx.x < o) red[threadIdx.x] += red[threadIdx.x + o];
        __syncthreads();
    }
    if (threadIdx.x == 0) out[r] = g[r] * rsqrtf(red[0]);
}

// ----------- tensor-core batched attmm: T[b*100+m, n] = att @ sW --------------
__global__ __launch_bounds__(256) void attmm_tc_kernel(
    const __half* __restrict__ att16,
    const __half* __restrict__ sWT,
    __half* __restrict__ T)
{
    __shared__ __align__(16) char smem[32 * 1024];
    const uint32_t As = smem_u32(smem);
    const uint32_t Bs = As + 16384;
    const int b    = blockIdx.y;
    const int ncol = blockIdx.x * 128;
    const int tid  = threadIdx.x;
    const int lane = tid & 31;
    const int wid  = tid >> 5;
    const int wm   = wid >> 1;
    const int wn   = wid & 1;

    #pragma unroll
    for (int it = 0; it < 4; ++it) {
        int e = tid + it * 256;
        int r = e >> 3, j = e & 7;
        const __half* src = att16 + ((size_t)(b * 128 + r)) * 64 + j * 8;
        uint32_t dst = As + r * 128 + ((j ^ (r & 7)) << 4);
        asm volatile("cp.async.cg.shared.global [%0], [%1], 16;"
                     :: "r"(dst), "l"(src) : "memory");
    }
    asm volatile("cp.async.commit_group;" ::: "memory");

    {
        const uint32_t* swt32 = reinterpret_cast<const uint32_t*>(sWT);
        #pragma unroll
        for (int i = 0; i < 16; ++i) {
            int n = wid * 16 + i;
            int j = lane;
            uint32_t val = 0;
            if (j < 25)
                val = swt32[(size_t)(ncol + n) * 3200 + b * 25 + j];
            uint32_t dst = Bs + n * 128 + ((((j >> 2) ^ (n & 7)) << 4) | ((j & 3) * 4));
            asm volatile("st.shared.b32 [%0], %1;" :: "r"(dst), "r"(val) : "memory");
        }
    }
    asm volatile("cp.async.wait_group 0;" ::: "memory");
    __syncthreads();

    float acc[2][8][4];
    #pragma unroll
    for (int a = 0; a < 2; a++)
        #pragma unroll
        for (int n = 0; n < 8; n++)
            #pragma unroll
            for (int c = 0; c < 4; c++) acc[a][n][c] = 0.f;

    const int rA = wm * 32 + (lane & 15);
    const int rB = wn * 64 + (lane & 7);
    #pragma unroll
    for (int ks = 0; ks < 4; ++ks) {
        uint32_t af[2][4], bf[8][2];
        #pragma unroll
        for (int mt = 0; mt < 2; ++mt) {
            int r = rA + mt * 16;
            int ch = ks * 2 + (lane >> 4);
            uint32_t addr = As + r * 128 + ((ch ^ (r & 7)) << 4);
            asm volatile("ldmatrix.sync.aligned.m8n8.x4.shared.b16 "
                         "{%0,%1,%2,%3}, [%4];"
                         : "=r"(af[mt][0]), "=r"(af[mt][1]),
                           "=r"(af[mt][2]), "=r"(af[mt][3])
                         : "r"(addr));
        }
        #pragma unroll
        for (int np = 0; np < 4; ++np) {
            int tile = np * 2 + (lane >> 4);
            int r = rB + tile * 8;
            int ch = ks * 2 + ((lane >> 3) & 1);
            uint32_t addr = Bs + r * 128 + ((ch ^ (r & 7)) << 4);
            asm volatile("ldmatrix.sync.aligned.m8n8.x4.shared.b16 "
                         "{%0,%1,%2,%3}, [%4];"
                         : "=r"(bf[np * 2][0]), "=r"(bf[np * 2][1]),
                           "=r"(bf[np * 2 + 1][0]), "=r"(bf[np * 2 + 1][1])
                         : "r"(addr));
        }
        #pragma unroll
        for (int mt = 0; mt < 2; ++mt)
            #pragma unroll
            for (int nt = 0; nt < 8; ++nt) {
                asm volatile(
                    "mma.sync.aligned.m16n8k16.row.col.f32.f16.f16.f32 "
                    "{%0,%1,%2,%3}, {%4,%5,%6,%7}, {%8,%9}, {%0,%1,%2,%3};"
                    : "+f"(acc[mt][nt][0]), "+f"(acc[mt][nt][1]),
                      "+f"(acc[mt][nt][2]), "+f"(acc[mt][nt][3])
                    : "r"(af[mt][0]), "r"(af[mt][1]),
                      "r"(af[mt][2]), "r"(af[mt][3]),
                      "r"(bf[nt][0]), "r"(bf[nt][1]));
            }
    }

    #pragma unroll
    for (int mt = 0; mt < 2; ++mt) {
        int m0 = wm * 32 + mt * 16 + (lane >> 2);
        #pragma unroll
        for (int h = 0; h < 2; ++h) {
            int m = m0 + h * 8;
            if (m >= NI) continue;
            size_t rowoff = (size_t)(b * NI + m) * OBJ;
            #pragma unroll
            for (int nt = 0; nt < 8; ++nt) {
                int col = ncol + wn * 64 + nt * 8 + (lane & 3) * 2;
                *reinterpret_cast<__half2*>(T + rowoff + col) =
                    __floats2half2_rn(acc[mt][nt][h * 2 + 0], acc[mt][nt][h * 2 + 1]);
            }
        }
    }
}

// ================ fp16 GEMM 128x128 (s_proj; handles K tails) =================
__global__ __launch_bounds__(256, 2) void gemm_mma_h(
    const __half* __restrict__ A, const __half* __restrict__ Bm,
    const float* __restrict__ scale, const float* __restrict__ bias,
    __half* __restrict__ C,
    int K, int lda, int ldb, int ldc)
{
    extern __shared__ __align__(128) char dynsmem[];
    const uint32_t sbase = smem_u32(dynsmem);
    const int tid  = threadIdx.x;
    const int lane = tid & 31;
    const int wid  = tid >> 5;
    const int wm   = wid >> 2;
    const int wn   = wid & 3;
    const int rowBase = blockIdx.y * 128;
    const int colBase = blockIdx.x * 128;

    const __half* Ablk = A  + (size_t)rowBase * lda;
    const __half* Bblk = Bm + (size_t)colBase * ldb;
    const int KT = (K + 63) / 64;

    auto load_chunk = [&](int L) {
        const int s = L % NST;
        const int k0 = L * 64;
        const uint32_t stage = sbase + s * STAGE_BYTES;
        const bool tail = (k0 + 64 > K);
        #pragma unroll
        for (int it = 0; it < 8; ++it) {
            int t = tid + it * 256;
            int which = t >> 10;
            int r = (t >> 3) & 127;
            int j = t & 7;
            int gk = k0 + j * 8;
            const __half* src = (which ? Bblk + (size_t)r * ldb
                                       : Ablk + (size_t)r * lda) + gk;
            uint32_t dst = stage + which * 16384 + r * 128 + ((j ^ (r & 7)) << 4);
            if (!tail) {
                asm volatile("cp.async.cg.shared.global [%0], [%1], 16;"
                             :: "r"(dst), "l"(src) : "memory");
            } else {
                uint32_t w[4];
                #pragma unroll
                for (int u = 0; u < 4; ++u) {
                    __half lo = (gk + 2 * u     < K) ? src[2 * u]     : __half(0.f);
                    __half hi = (gk + 2 * u + 1 < K) ? src[2 * u + 1] : __half(0.f);
                    __half2 h2 = __halves2half2(lo, hi);
                    w[u] = *reinterpret_cast<uint32_t*>(&h2);
                }
                asm volatile("st.shared.v4.b32 [%0], {%1,%2,%3,%4};"
                             :: "r"(dst), "r"(w[0]), "r"(w[1]), "r"(w[2]), "r"(w[3])
                             : "memory");
            }
        }
    };

    #pragma unroll
    for (int p = 0; p < NST - 1; ++p) {
        if (p < KT) load_chunk(p);
        asm volatile("cp.async.commit_group;" ::: "memory");
    }

    float acc[4][4][4];
    #pragma unroll
    for (int a = 0; a < 4; a++)
        #pragma unroll
        for (int b = 0; b < 4; b++)
            #pragma unroll
            for (int c = 0; c < 4; c++) acc[a][b][c] = 0.f;

    for (int c = 0; c < KT; ++c) {
        asm volatile("cp.async.wait_group 1;" ::: "memory");
        __syncthreads();

        const int L = c + NST - 1;
        if (L < KT) load_chunk(L);
        asm volatile("cp.async.commit_group;" ::: "memory");

        const uint32_t ast = sbase + (c % NST) * STAGE_BYTES;
        const uint32_t bst = ast + 16384;

        #pragma unroll
        for (int ks = 0; ks < 4; ++ks) {
            uint32_t af[4][4], bf[4][2];
            #pragma unroll
            for (int mt = 0; mt < 4; ++mt) {
                int r = wm * 64 + mt * 16 + (lane & 15);
                int ch = ks * 2 + (lane >> 4);
                uint32_t addr = ast + r * 128 + ((ch ^ (r & 7)) << 4);
                asm volatile("ldmatrix.sync.aligned.m8n8.x4.shared.b16 "
                             "{%0,%1,%2,%3}, [%4];"
                             : "=r"(af[mt][0]), "=r"(af[mt][1]),
                               "=r"(af[mt][2]), "=r"(af[mt][3])
                             : "r"(addr));
            }
            #pragma unroll
            for (int np = 0; np < 2; ++np) {
                int tile = np * 2 + (lane >> 4);
                int half_k = (lane >> 3) & 1;
                int r = wn * 32 + tile * 8 + (lane & 7);
                int ch = ks * 2 + half_k;
                uint32_t addr = bst + r * 128 + ((ch ^ (r & 7)) << 4);
                asm volatile("ldmatrix.sync.aligned.m8n8.x4.shared.b16 "
                             "{%0,%1,%2,%3}, [%4];"
                             : "=r"(bf[np * 2][0]), "=r"(bf[np * 2][1]),
                               "=r"(bf[np * 2 + 1][0]), "=r"(bf[np * 2 + 1][1])
                             : "r"(addr));
            }
            #pragma unroll
            for (int mt = 0; mt < 4; ++mt)
                #pragma unroll
                for (int nt = 0; nt < 4; ++nt) {
                    asm volatile(
                        "mma.sync.aligned.m16n8k16.row.col.f32.f16.f16.f32 "
                        "{%0,%1,%2,%3}, {%4,%5,%6,%7}, {%8,%9}, {%0,%1,%2,%3};"
                        : "+f"(acc[mt][nt][0]), "+f"(acc[mt][nt][1]),
                          "+f"(acc[mt][nt][2]), "+f"(acc[mt][nt][3])
                        : "r"(af[mt][0]), "r"(af[mt][1]),
                          "r"(af[mt][2]), "r"(af[mt][3]),
                          "r"(bf[nt][0]), "r"(bf[nt][1]));
                }
        }
    }

    #pragma unroll
    for (int mt = 0; mt < 4; ++mt) {
        int r0 = rowBase + wm * 64 + mt * 16 + (lane >> 2);
        #pragma unroll
        for (int nt = 0; nt < 4; ++nt) {
            int col = colBase + wn * 32 + nt * 8 + (lane & 3) * 2;
            float2 sc = *reinterpret_cast<const float2*>(scale + col);
            float2 bi = *reinterpret_cast<const float2*>(bias + col);
            #pragma unroll
            for (int h = 0; h < 2; ++h) {
                int row = r0 + h * 8;
                float ox = fmaxf(acc[mt][nt][h * 2 + 0] * sc.x + bi.x, 0.f);
                float oy = fmaxf(acc[mt][nt][h * 2 + 1] * sc.y + bi.y, 0.f);
                *reinterpret_cast<__half2*>(C + (size_t)row * ldc + col) =
                    __floats2half2_rn(ox, oy);
            }
        }
    }
}

// ====== fp16 GEMM 256x128, 4-stage, frag double-buffered (sWT) ================
// MODE 2: C(half) = acc (raw)
template<int MODE>
__global__ __launch_bounds__(256, 1) void gemm_mma_h2(
    const __half* __restrict__ A, const __half* __restrict__ Bm,
    const float* __restrict__ scale, const float* __restrict__ bias,
    const float* __restrict__ resid, const __half* __restrict__ Tadd,
    void* __restrict__ Cv,
    int K, int lda, int ldb, int ldc)
{
    extern __shared__ __align__(128) char dynsmem[];
    const uint32_t sbase = smem_u32(dynsmem);
    const int tid  = threadIdx.x;
    const int lane = tid & 31;
    const int wid  = tid >> 5;
    const int wm   = wid >> 1;
    const int wn   = wid & 1;
    const int rowBase = blockIdx.y * 256;
    const int colBase = blockIdx.x * 128;

    const __half* Ablk = A  + (size_t)rowBase * lda;
    const __half* Bblk = Bm + (size_t)colBase * ldb;
    const int KT = K / 64;

    const int rA = wm * 64 + (lane & 15);
    const int rB = wn * 64 + (lane & 7);
    const int chA_half = (lane >> 4);
    const int tB_base  = (lane >> 4);
    const int chB_half = (lane >> 3) & 1;

    auto load_chunk = [&](int L) {
        const int s = L % NST2;
        const int k0 = L * 64;
        const uint32_t stage = sbase + s * STAGE2_BYTES;
        #pragma unroll
        for (int it = 0; it < 12; ++it) {
            int t = tid + it * 256;
            bool isB = t >= 2048;
            int tt = isB ? t - 2048 : t;
            int r = tt >> 3;
            int j = tt & 7;
            int gk = k0 + j * 8;
            const __half* src = (isB ? Bblk + (size_t)r * ldb
                                     : Ablk + (size_t)r * lda) + gk;
            uint32_t dst = stage + (isB ? 32768 : 0) + r * 128 + ((j ^ (r & 7)) << 4);
            asm volatile("cp.async.cg.shared.global [%0], [%1], 16;"
                         :: "r"(dst), "l"(src) : "memory");
        }
    };

    uint32_t af[2][4][4], bf[2][8][2];

    auto load_frags = [&](uint32_t ast, uint32_t bst, int ks, int pb) {
        #pragma unroll
        for (int mt = 0; mt < 4; ++mt) {
            int r = rA + mt * 16;
            int ch = ks * 2 + chA_half;
            uint32_t addr = ast + r * 128 + ((ch ^ (r & 7)) << 4);
            asm volatile("ldmatrix.sync.aligned.m8n8.x4.shared.b16 "
                         "{%0,%1,%2,%3}, [%4];"
                         : "=r"(af[pb][mt][0]), "=r"(af[pb][mt][1]),
                           "=r"(af[pb][mt][2]), "=r"(af[pb][mt][3])
                         : "r"(addr));
        }
        #pragma unroll
        for (int np = 0; np < 4; ++np) {
            int tile = np * 2 + tB_base;
            int r = rB + tile * 8;
            int ch = ks * 2 + chB_half;
            uint32_t addr = bst + r * 128 + ((ch ^ (r & 7)) << 4);
            asm volatile("ldmatrix.sync.aligned.m8n8.x4.shared.b16 "
                         "{%0,%1,%2,%3}, [%4];"
                         : "=r"(bf[pb][np * 2][0]), "=r"(bf[pb][np * 2][1]),
                           "=r"(bf[pb][np * 2 + 1][0]), "=r"(bf[pb][np * 2 + 1][1])
                         : "r"(addr));
        }
    };

    #pragma unroll
    for (int p = 0; p < NST2 - 1; ++p) {
        load_chunk(p);
        asm volatile("cp.async.commit_group;" ::: "memory");
    }
    asm volatile("cp.async.wait_group 2;" ::: "memory");
    __syncthreads();
    load_frags(sbase, sbase + 32768, 0, 0);

    float acc[4][8][4];
    #pragma unroll
    for (int a = 0; a < 4; a++)
        #pragma unroll
        for (int b = 0; b < 8; b++)
            #pragma unroll
            for (int c = 0; c < 4; c++) acc[a][b][c] = 0.f;

    for (int c = 0; c < KT; ++c) {
        asm volatile("cp.async.wait_group 1;" ::: "memory");
        __syncthreads();

        const uint32_t ast  = sbase + (c % NST2) * STAGE2_BYTES;
        const uint32_t bst  = ast + 32768;
        const uint32_t nast = sbase + ((c + 1) % NST2) * STAGE2_BYTES;
        const uint32_t nbst = nast + 32768;
        const int L = c + NST2 - 1;

        #pragma unroll
        for (int ks = 0; ks < 4; ++ks) {
            if (ks == 1) {
                if (L < KT) load_chunk(L);
                asm volatile("cp.async.commit_group;" ::: "memory");
            }
            if (ks < 3)            load_frags(ast, bst, ks + 1, (ks + 1) & 1);
            else if (c + 1 < KT)   load_frags(nast, nbst, 0, 0);
            const int pb = ks & 1;
            #pragma unroll
            for (int mt = 0; mt < 4; ++mt)
                #pragma unroll
                for (int nt = 0; nt < 8; ++nt) {
                    asm volatile(
                        "mma.sync.aligned.m16n8k16.row.col.f32.f16.f16.f32 "
                        "{%0,%1,%2,%3}, {%4,%5,%6,%7}, {%8,%9}, {%0,%1,%2,%3};"
                        : "+f"(acc[mt][nt][0]), "+f"(acc[mt][nt][1]),
                          "+f"(acc[mt][nt][2]), "+f"(acc[mt][nt][3])
                        : "r"(af[pb][mt][0]), "r"(af[pb][mt][1]),
                          "r"(af[pb][mt][2]), "r"(af[pb][mt][3]),
                          "r"(bf[pb][nt][0]), "r"(bf[pb][nt][1]));
                }
        }
    }

    #pragma unroll
    for (int mt = 0; mt < 4; ++mt) {
        int r0 = rowBase + wm * 64 + mt * 16 + (lane >> 2);
        #pragma unroll
        for (int nt = 0; nt < 8; ++nt) {
            int col = colBase + wn * 64 + nt * 8 + (lane & 3) * 2;
            #pragma unroll
            for (int h = 0; h < 2; ++h) {
                int row = r0 + h * 8;
                __half* C = (__half*)Cv;
                *reinterpret_cast<__half2*>(C + (size_t)row * ldc + col) =
                    __floats2half2_rn(acc[mt][nt][h * 2 + 0], acc[mt][nt][h * 2 + 1]);
            }
        }
    }
}

// ====== fp16 GEMM 128x256, 512 threads, 4 warps/SMSP (iproj / comb) ===========
// 16 warps in 4x4, warp tile 32x64, single-buffered frags.
// MODE 0: C(half)  = relu(acc*scale+bias)
// MODE 3: C(float) = resid + relu(scale*(acc + T) + bias)
template<int MODE>
__global__ __launch_bounds__(512, 1) void gemm_mma_w(
    const __half* __restrict__ A, const __half* __restrict__ Bm,
    const float* __restrict__ scale, const float* __restrict__ bias,
    const float* __restrict__ resid, const __half* __restrict__ Tadd,
    void* __restrict__ Cv,
    int K, int lda, int ldb, int ldc)
{
    extern __shared__ __align__(128) char dynsmem[];
    const uint32_t sbase = smem_u32(dynsmem);
    const int tid  = threadIdx.x;
    const int lane = tid & 31;
    const int wid  = tid >> 5;          // 0..15
    const int wm   = wid >> 2;          // 0..3 (32 rows each)
    const int wn   = wid & 3;           // 0..3 (64 cols each)
    const int rowBase = blockIdx.y * 128;
    const int colBase = blockIdx.x * 256;

    const __half* Ablk = A  + (size_t)rowBase * lda;
    const __half* Bblk = Bm + (size_t)colBase * ldb;
    const int KT = K / 64;

    const int rA = wm * 32 + (lane & 15);
    const int rB = wn * 64 + (lane & 7);
    const int chA_half = (lane >> 4);
    const int tB_base  = (lane >> 4);
    const int chB_half = (lane >> 3) & 1;

    auto load_chunk = [&](int L) {
        const int s = L % NSTW;
        const int k0 = L * 64;
        const uint32_t stage = sbase + s * STAGEW_BYTES;
        #pragma unroll
        for (int it = 0; it < 6; ++it) {
            int t = tid + it * 512;            // 0..3071
            bool isB = t >= 1024;              // A: 128 rows, B: 256 rows
            int tt = isB ? t - 1024 : t;
            int r = tt >> 3;
            int j = tt & 7;
            int gk = k0 + j * 8;
            const __half* src = (isB ? Bblk + (size_t)r * ldb
                                     : Ablk + (size_t)r * lda) + gk;
            uint32_t dst = stage + (isB ? 16384 : 0) + r * 128 + ((j ^ (r & 7)) << 4);
            asm volatile("cp.async.cg.shared.global [%0], [%1], 16;"
                         :: "r"(dst), "l"(src) : "memory");
        }
    };

    #pragma unroll
    for (int p = 0; p < NSTW - 1; ++p) {
        load_chunk(p);
        asm volatile("cp.async.commit_group;" ::: "memory");
    }

    float acc[2][8][4];
    #pragma unroll
    for (int a = 0; a < 2; a++)
        #pragma unroll
        for (int b = 0; b < 8; b++)
            #pragma unroll
            for (int c = 0; c < 4; c++) acc[a][b][c] = 0.f;

    for (int c = 0; c < KT; ++c) {
        asm volatile("cp.async.wait_group 2;" ::: "memory");   // chunk c resident
        __syncthreads();

        const uint32_t ast = sbase + (c % NSTW) * STAGEW_BYTES;
        const uint32_t bst = ast + 16384;
        const int L = c + NSTW - 1;

        #pragma unroll
        for (int ks = 0; ks < 4; ++ks) {
            if (ks == 1) {
                if (L < KT) load_chunk(L);
                asm volatile("cp.async.commit_group;" ::: "memory");
            }
            uint32_t af[2][4], bf[8][2];
            #pragma unroll
            for (int mt = 0; mt < 2; ++mt) {
                int r = rA + mt * 16;
                int ch = ks * 2 + chA_half;
                uint32_t addr = ast + r * 128 + ((ch ^ (r & 7)) << 4);
                asm volatile("ldmatrix.sync.aligned.m8n8.x4.shared.b16 "
                             "{%0,%1,%2,%3}, [%4];"
                             : "=r"(af[mt][0]), "=r"(af[mt][1]),
                               "=r"(af[mt][2]), "=r"(af[mt][3])
                             : "r"(addr));
            }
            #pragma unroll
            for (int np = 0; np < 4; ++np) {
                int tile = np * 2 + tB_base;
                int r = rB + tile * 8;
                int ch = ks * 2 + chB_half;
                uint32_t addr = bst + r * 128 + ((ch ^ (r & 7)) << 4);
                asm volatile("ldmatrix.sync.aligned.m8n8.x4.shared.b16 "
                             "{%0,%1,%2,%3}, [%4];"
                             : "=r"(bf[np * 2][0]), "=r"(bf[np * 2][1]),
                               "=r"(bf[np * 2 + 1][0]), "=r"(bf[np * 2 + 1][1])
                             : "r"(addr));
            }
            #pragma unroll
            for (int mt = 0; mt < 2; ++mt)
                #pragma unroll
                for (int nt = 0; nt < 8; ++nt) {
                    asm volatile(
                        "mma.sync.aligned.m16n8k16.row.col.f32.f16.f16.f32 "
                        "{%0,%1,%2,%3}, {%4,%5,%6,%7}, {%8,%9}, {%0,%1,%2,%3};"
                        : "+f"(acc[mt][nt][0]), "+f"(acc[mt][nt][1]),
                          "+f"(acc[mt][nt][2]), "+f"(acc[mt][nt][3])
                        : "r"(af[mt][0]), "r"(af[mt][1]),
                          "r"(af[mt][2]), "r"(af[mt][3]),
                          "r"(bf[nt][0]), "r"(bf[nt][1]));
                }
        }
    }

    #pragma unroll
    for (int mt = 0; mt < 2; ++mt) {
        int r0 = rowBase + wm * 32 + mt * 16 + (lane >> 2);
        #pragma unroll
        for (int nt = 0; nt < 8; ++nt) {
            int col = colBase + wn * 64 + nt * 8 + (lane & 3) * 2;
            float2 sc = *reinterpret_cast<const float2*>(scale + col);
            float2 bi = *reinterpret_cast<const float2*>(bias + col);
            #pragma unroll
            for (int h = 0; h < 2; ++h) {
                int row = r0 + h * 8;
                float ax = acc[mt][nt][h * 2 + 0];
                float ay = acc[mt][nt][h * 2 + 1];
                if (MODE == 0) {
                    float ox = fmaxf(ax * sc.x + bi.x, 0.f);
                    float oy = fmaxf(ay * sc.y + bi.y, 0.f);
                    __half* C = (__half*)Cv;
                    *reinterpret_cast<__half2*>(C + (size_t)row * ldc + col) =
                        __floats2half2_rn(ox, oy);
                } else {  // MODE 3
                    __half2 th = *reinterpret_cast<const __half2*>(
                        Tadd + (size_t)row * ldc + col);
                    float2 tf = __half22float2(th);
                    float ox = fmaxf((ax + tf.x) * sc.x + bi.x, 0.f);
                    float oy = fmaxf((ay + tf.y) * sc.y + bi.y, 0.f);
                    float2 rr = *reinterpret_cast<const float2*>(
                        resid + (size_t)row * ldc + col);
                    float2 o = {ox + rr.x, oy + rr.y};
                    float* C = (float*)Cv;
                    *reinterpret_cast<float2*>(C + (size_t)row * ldc + col) = o;
                }
            }
        }
    }
}

// ---------------------------------------------------------------------------
extern "C" void kernel_launch(void* const* d_in, const int* in_sizes, int n_in,
                              void* d_out, int out_size)
{
    const float* i_in   = (const float*)d_in[0];
    const float* s_in   = (const float*)d_in[1];
    const float* pi_in  = (const float*)d_in[2];
    const float* ps_in  = (const float*)d_in[3];
    const int*   mask_s = (const int*)  d_in[4];
    const float* vi = (const float*)d_in[5];
    const float* gi = (const float*)d_in[6];
    const float* bi = (const float*)d_in[7];
    const float* vs = (const float*)d_in[8];
    const float* gs = (const float*)d_in[9];
    const float* bs = (const float*)d_in[10];
    const float* vc = (const float*)d_in[11];
    const float* gc = (const float*)d_in[12];
    const float* bc = (const float*)d_in[13];
    float* out = (float*)d_out;

    float *si_p, *ss_p, *sc_p;
    __half *att16_p, *sproj_p, *sWT_p, *T_p, *iproj_p;
    __half *i16_p, *s16_p, *vi16_p, *vs16_p, *vc16_p;
    cudaGetSymbolAddress((void**)&att16_p, g_att16);
    cudaGetSymbolAddress((void**)&sproj_p, g_sproj);
    cudaGetSymbolAddress((void**)&sWT_p,   g_sWT);
    cudaGetSymbolAddress((void**)&T_p,     g_T);
    cudaGetSymbolAddress((void**)&iproj_p, g_iproj);
    cudaGetSymbolAddress((void**)&si_p,    g_si);
    cudaGetSymbolAddress((void**)&ss_p,    g_ss);
    cudaGetSymbolAddress((void**)&sc_p,    g_sc);
    cudaGetSymbolAddress((void**)&i16_p,   g_i16);
    cudaGetSymbolAddress((void**)&s16_p,   g_s16);
    cudaGetSymbolAddress((void**)&vi16_p,  g_vi16);
    cudaGetSymbolAddress((void**)&vs16_p,  g_vs16);
    cudaGetSymbolAddress((void**)&vc16_p,  g_vc16);

    cudaFuncSetAttribute(gemm_mma_h,     cudaFuncAttributeMaxDynamicSharedMemorySize, SMEM_DYN);
    cudaFuncSetAttribute(gemm_mma_h2<2>, cudaFuncAttributeMaxDynamicSharedMemorySize, SMEM_DYN2);
    cudaFuncSetAttribute(gemm_mma_w<0>,  cudaFuncAttributeMaxDynamicSharedMemorySize, SMEM_DYNW);
    cudaFuncSetAttribute(gemm_mma_w<3>,  cudaFuncAttributeMaxDynamicSharedMemorySize, SMEM_DYNW);

    // Streams + events (created once on the uncaptured correctness call)
    static cudaStream_t s1 = nullptr, s2 = nullptr;
    static cudaEvent_t evRoot = nullptr, evVC = nullptr, evW1 = nullptr, evI = nullptr;
    if (s1 == nullptr) {
        cudaStreamCreateWithFlags(&s1, cudaStreamNonBlocking);
        cudaStreamCreateWithFlags(&s2, cudaStreamNonBlocking);
        cudaEventCreateWithFlags(&evRoot, cudaEventDisableTiming);
        cudaEventCreateWithFlags(&evVC,   cudaEventDisableTiming);
        cudaEventCreateWithFlags(&evW1,   cudaEventDisableTiming);
        cudaEventCreateWithFlags(&evI,    cudaEventDisableTiming);
    }

    // ---- fork ------------------------------------------------------------------
    cudaEventRecord(evRoot, 0);
    cudaStreamWaitEvent(s1, evRoot, 0);
    cudaStreamWaitEvent(s2, evRoot, 0);

    // s1: weight converts (vi, vc), then scales si/sc + attention
    prep_vv_kernel<<<2048, 256, 0, s1>>>(vi, vi16_p, vc, vc16_p);
    cudaEventRecord(evVC, s1);
    prep2b_kernel<<<P2_BLOCKS, 256, 0, s1>>>(vi, gi, si_p, vc, gc, sc_p,
                                             pi_in, ps_in, mask_s, att16_p);
    cudaEventRecord(evW1, s1);

    // s2: i -> fp16, then i_proj (128x256 wide kernel)
    prep_i_kernel<<<4096, 256, 0, s2>>>(i_in, i16_p);
    cudaStreamWaitEvent(s2, evW1, 0);
    gemm_mma_w<0><<<dim3(PROJ / 256, MI / 128), 512, SMEM_DYNW, s2>>>(
        i16_p, vi16_p, si_p, bi, nullptr, nullptr, iproj_p,
        OBJ, OBJ, OBJ, PROJ);
    cudaEventRecord(evI, s2);

    // 0: s-side chain
    prep_s_kernel<<<PS_BLOCKS, 256>>>(s_in, s16_p, vs, vs16_p, gs, ss_p);

    gemm_mma_h<<<dim3(PROJ / 128, MS / 128), 256, SMEM_DYN>>>(
        s16_p, vs16_p, ss_p, bs, sproj_p, SEM, SEMP, SEMP, PROJ);

    cudaStreamWaitEvent(0, evVC, 0);
    gemm_mma_h2<2><<<dim3(MS / 128, OBJ / 256), 256, SMEM_DYN2>>>(
        vc16_p + PROJ, sproj_p, nullptr, nullptr, nullptr, nullptr, sWT_p,
        PROJ, 2 * PROJ, PROJ, MS);

    cudaStreamWaitEvent(0, evW1, 0);
    attmm_tc_kernel<<<dim3(OBJ / 128, B_), 256>>>(att16_p, sWT_p, T_p);

    // join: comb (128x256 wide kernel) needs iproj (s2) + T (0)
    cudaStreamWaitEvent(0, evI, 0);
    gemm_mma_w<3><<<dim3(OBJ / 256, MI / 128), 512, SMEM_DYNW>>>(
        iproj_p, vc16_p, sc_p, bc, i_in, T_p, out,
        PROJ, PROJ, 2 * PROJ, OBJ);
}

// round 17
// speedup vs baseline: 1.0859x; 1.0859x over previous
#include <cuda_runtime.h>
#include <cuda_fp16.h>
#include <cstdint>
#include <cstddef>

// Problem constants
constexpr int B_   = 128;
constexpr int NI   = 100;
constexpr int NS   = 50;
constexpr int OBJ  = 2048;
constexpr int SEM  = 300;
constexpr int SEMP = 304;
constexpr int PROJ = 1024;
constexpr int MI = B_ * NI;   // 12800
constexpr int MS = B_ * NS;   // 6400

// 128x128 GEMM pipeline (s_proj)
constexpr int NST = 3;
constexpr int STAGE_BYTES = 2 * 128 * 128;
constexpr int SMEM_DYN = NST * STAGE_BYTES;    // 96 KB

// 256x128 GEMM pipeline (big GEMMs)
constexpr int NST2 = 4;
constexpr int STAGE2_BYTES = (256 + 128) * 128;
constexpr int SMEM_DYN2 = NST2 * STAGE2_BYTES; // 192 KB

// ---------------- scratch (device globals; no runtime allocation) ------------
__device__ __align__(16) __half g_att16[(size_t)B_ * 128 * 64];
__device__ __align__(16) __half g_sproj[(size_t)MS * PROJ];
__device__ __align__(16) __half g_sWT  [(size_t)OBJ * MS];
__device__ __align__(16) __half g_T    [(size_t)MI * OBJ];
__device__ __align__(16) __half g_iproj[(size_t)MI * PROJ];
__device__ __align__(16) __half g_i16  [(size_t)MI * OBJ];
__device__ __align__(16) __half g_s16  [(size_t)MS * SEMP];
__device__ __align__(16) __half g_vi16 [(size_t)PROJ * OBJ];
__device__ __align__(16) __half g_vs16 [(size_t)PROJ * SEMP];
__device__ __align__(16) __half g_vc16 [(size_t)OBJ * 2 * PROJ];
__device__ __align__(16) float  g_si[PROJ];
__device__ __align__(16) float  g_ss[PROJ];
__device__ __align__(16) float  g_sc[OBJ];

// ======================= helpers ==============================================
__device__ __forceinline__ uint32_t smem_u32(const void* p) {
    uint32_t a;
    asm("{ .reg .u64 t; cvta.to.shared.u64 t, %1; cvt.u32.u64 %0, t; }"
        : "=r"(a) : "l"(p));
    return a;
}

// ---------------- prep_i: fp16 convert (generic range, low-reg) ---------------
__global__ void prep_i_kernel(const float* __restrict__ src, __half* __restrict__ dst,
                              int n4)
{
    for (int t = blockIdx.x * blockDim.x + threadIdx.x; t < n4;
         t += gridDim.x * blockDim.x) {
        float4 v = reinterpret_cast<const float4*>(src)[t];
        __half2* d = reinterpret_cast<__half2*>(dst + (size_t)t * 4);
        d[0] = __floats2half2_rn(v.x, v.y);
        d[1] = __floats2half2_rn(v.z, v.w);
    }
}

// ------- prep_s: convert s + vs to fp16 AND rownorm ss (gates sproj only) -----
constexpr int PS_NS  = MS * SEM / 4;
constexpr int PS_NVS = PROJ * SEM / 4;
constexpr int PS_TOT = PS_NS + PS_NVS;
constexpr int PS_CONV_BLOCKS = 1024;
constexpr int PS_BLOCKS = PS_CONV_BLOCKS + PROJ;

__global__ void prep_s_kernel(const float* __restrict__ s,  __half* __restrict__ s16,
                              const float* __restrict__ vs, __half* __restrict__ vs16,
                              const float* __restrict__ gs, float* __restrict__ ss)
{
    int blk = blockIdx.x;
    if (blk < PS_CONV_BLOCKS) {
        for (int t = blk * blockDim.x + threadIdx.x; t < PS_TOT;
             t += PS_CONV_BLOCKS * 256) {
            const float* src; __half* dst; int j = t;
            if (j < PS_NS) { src = s;  dst = s16; }
            else           { j -= PS_NS; src = vs; dst = vs16; }
            int row = j / 75, c = j % 75;
            float4 v = reinterpret_cast<const float4*>(src)[j];
            __half2* d = reinterpret_cast<__half2*>(dst + (size_t)row * SEMP + c * 4);
            d[0] = __floats2half2_rn(v.x, v.y);
            d[1] = __floats2half2_rn(v.z, v.w);
        }
        return;
    }
    int r = blk - PS_CONV_BLOCKS;
    float s2 = 0.f;
    for (int k = threadIdx.x; k < SEM; k += blockDim.x) {
        float x = vs[(size_t)r * SEM + k];
        s2 += x * x;
    }
    __shared__ float red[256];
    red[threadIdx.x] = s2;
    __syncthreads();
    #pragma unroll
    for (int o = 128; o > 0; o >>= 1) {
        if (threadIdx.x < o) red[threadIdx.x] += red[threadIdx.x + o];
        __syncthreads();
    }
    if (threadIdx.x == 0) ss[r] = gs[r] * rsqrtf(red[0]);
}

// ------- prep_vv: fp16 convert of vi + vc --------------------------------------
constexpr int PV_NVI = PROJ * OBJ / 4;
constexpr int PV_NVC = OBJ * 2 * PROJ / 4;
constexpr int PV_TOT = PV_NVI + PV_NVC;

__global__ void prep_vv_kernel(const float* __restrict__ vi, __half* __restrict__ vi16,
                               const float* __restrict__ vc, __half* __restrict__ vc16)
{
    for (int t = blockIdx.x * blockDim.x + threadIdx.x; t < PV_TOT;
         t += gridDim.x * blockDim.x) {
        const float* src; __half* dst; int j = t;
        if (j < PV_NVI) { src = vi; dst = vi16; }
        else            { j -= PV_NVI; src = vc; dst = vc16; }
        float4 v = reinterpret_cast<const float4*>(src)[j];
        __half2* d = reinterpret_cast<__half2*>(dst + (size_t)j * 4);
        d[0] = __floats2half2_rn(v.x, v.y);
        d[1] = __floats2half2_rn(v.z, v.w);
    }
}

// ------- prep2b: rownorm si + sc, attention softmax ---------------------------
constexpr int P2_SI = PROJ;
constexpr int P2_SC = OBJ;
constexpr int P2_ATT = B_ * 128 / 256;
constexpr int P2_BLOCKS = P2_SI + P2_SC + P2_ATT;

__global__ void prep2b_kernel(const float* __restrict__ vi, const float* __restrict__ gi,
                              float* __restrict__ si,
                              const float* __restrict__ vc, const float* __restrict__ gc,
                              float* __restrict__ sc,
                              const float* __restrict__ pi, const float* __restrict__ ps,
                              const int* __restrict__ mask_s, __half* __restrict__ att16)
{
    int blk = blockIdx.x;
    if (blk >= P2_SI + P2_SC) {
        int idx = (blk - P2_SI - P2_SC) * blockDim.x + threadIdx.x;
        int b = idx >> 7;
        int m = idx & 127;
        __half2* orow = reinterpret_cast<__half2*>(att16 + (size_t)idx * 64);
        if (m >= NI) {
            #pragma unroll
            for (int j = 0; j < 32; j++) orow[j] = __halves2half2(__half(0.f), __half(0.f));
            return;
        }
        int rix = b * NI + m;
        float px = pi[rix * 2 + 0];
        float py = pi[rix * 2 + 1];
        int mm = mask_s[b];
        const float* psb = ps + (size_t)b * NS * 2;

        float d[NS];
        float mx = -1e30f;
        #pragma unroll
        for (int j = 0; j < NS; j++) {
            float dx = px - psb[2 * j + 0];
            float dy = py - psb[2 * j + 1];
            d[j] = sqrtf(dx * dx + dy * dy);
            if (j < mm) mx = fmaxf(mx, d[j]);
        }
        float sum = 0.f;
        #pragma unroll
        for (int j = 0; j < NS; j++) {
            float e = (j < mm) ? __expf(d[j] - mx) : 0.f;
            d[j] = e;
            sum += e;
        }
        float inv = 1.f / sum;
        #pragma unroll
        for (int j = 0; j < 32; j++) {
            float lo = (2 * j     < NS) ? d[2 * j]     * inv : 0.f;
            float hi = (2 * j + 1 < NS) ? d[2 * j + 1] * inv : 0.f;
            orow[j] = __floats2half2_rn(lo, hi);
        }
        return;
    }
    const float *v, *g; float* out; int K, r;
    if (blk < P2_SI) { v = vi; g = gi; out = si; K = OBJ;      r = blk; }
    else             { v = vc; g = gc; out = sc; K = 2 * PROJ; r = blk - P2_SI; }

    float s = 0.f;
    for (int k = threadIdx.x; k < K; k += blockDim.x) {
        float x = v[(size_t)r * K + k];
        s += x * x;
    }
    __shared__ float red[256];
    red[threadIdx.x] = s;
    __syncthreads();
    #pragma unroll
    for (int o = 128; o > 0; o >>= 1) {
        if (threadIdx.x < o) red[threadIdx.x] += red[threadIdx.x + o];
        __syncthreads();
    }
    if (threadIdx.x == 0) out[r] = g[r] * rsqrtf(red[0]);
}

// ----------- tensor-core batched attmm: T[b*100+m, n] = att @ sW --------------
__global__ __launch_bounds__(256) void attmm_tc_kernel(
    const __half* __restrict__ att16,
    const __half* __restrict__ sWT,
    __half* __restrict__ T)
{
    __shared__ __align__(16) char smem[32 * 1024];
    const uint32_t As = smem_u32(smem);
    const uint32_t Bs = As + 16384;
    const int b    = blockIdx.y;
    const int ncol = blockIdx.x * 128;
    const int tid  = threadIdx.x;
    const int lane = tid & 31;
    const int wid  = tid >> 5;
    const int wm   = wid >> 1;
    const int wn   = wid & 1;

    #pragma unroll
    for (int it = 0; it < 4; ++it) {
        int e = tid + it * 256;
        int r = e >> 3, j = e & 7;
        const __half* src = att16 + ((size_t)(b * 128 + r)) * 64 + j * 8;
        uint32_t dst = As + r * 128 + ((j ^ (r & 7)) << 4);
        asm volatile("cp.async.cg.shared.global [%0], [%1], 16;"
                     :: "r"(dst), "l"(src) : "memory");
    }
    asm volatile("cp.async.commit_group;" ::: "memory");

    {
        const uint32_t* swt32 = reinterpret_cast<const uint32_t*>(sWT);
        #pragma unroll
        for (int i = 0; i < 16; ++i) {
            int n = wid * 16 + i;
            int j = lane;
            uint32_t val = 0;
            if (j < 25)
                val = swt32[(size_t)(ncol + n) * 3200 + b * 25 + j];
            uint32_t dst = Bs + n * 128 + ((((j >> 2) ^ (n & 7)) << 4) | ((j & 3) * 4));
            asm volatile("st.shared.b32 [%0], %1;" :: "r"(dst), "r"(val) : "memory");
        }
    }
    asm volatile("cp.async.wait_group 0;" ::: "memory");
    __syncthreads();

    float acc[2][8][4];
    #pragma unroll
    for (int a = 0; a < 2; a++)
        #pragma unroll
        for (int n = 0; n < 8; n++)
            #pragma unroll
            for (int c = 0; c < 4; c++) acc[a][n][c] = 0.f;

    const int rA = wm * 32 + (lane & 15);
    const int rB = wn * 64 + (lane & 7);
    #pragma unroll
    for (int ks = 0; ks < 4; ++ks) {
        uint32_t af[2][4], bf[8][2];
        #pragma unroll
        for (int mt = 0; mt < 2; ++mt) {
            int r = rA + mt * 16;
            int ch = ks * 2 + (lane >> 4);
            uint32_t addr = As + r * 128 + ((ch ^ (r & 7)) << 4);
            asm volatile("ldmatrix.sync.aligned.m8n8.x4.shared.b16 "
                         "{%0,%1,%2,%3}, [%4];"
                         : "=r"(af[mt][0]), "=r"(af[mt][1]),
                           "=r"(af[mt][2]), "=r"(af[mt][3])
                         : "r"(addr));
        }
        #pragma unroll
        for (int np = 0; np < 4; ++np) {
            int tile = np * 2 + (lane >> 4);
            int r = rB + tile * 8;
            int ch = ks * 2 + ((lane >> 3) & 1);
            uint32_t addr = Bs + r * 128 + ((ch ^ (r & 7)) << 4);
            asm volatile("ldmatrix.sync.aligned.m8n8.x4.shared.b16 "
                         "{%0,%1,%2,%3}, [%4];"
                         : "=r"(bf[np * 2][0]), "=r"(bf[np * 2][1]),
                           "=r"(bf[np * 2 + 1][0]), "=r"(bf[np * 2 + 1][1])
                         : "r"(addr));
        }
        #pragma unroll
        for (int mt = 0; mt < 2; ++mt)
            #pragma unroll
            for (int nt = 0; nt < 8; ++nt) {
                asm volatile(
                    "mma.sync.aligned.m16n8k16.row.col.f32.f16.f16.f32 "
                    "{%0,%1,%2,%3}, {%4,%5,%6,%7}, {%8,%9}, {%0,%1,%2,%3};"
                    : "+f"(acc[mt][nt][0]), "+f"(acc[mt][nt][1]),
                      "+f"(acc[mt][nt][2]), "+f"(acc[mt][nt][3])
                    : "r"(af[mt][0]), "r"(af[mt][1]),
                      "r"(af[mt][2]), "r"(af[mt][3]),
                      "r"(bf[nt][0]), "r"(bf[nt][1]));
            }
    }

    #pragma unroll
    for (int mt = 0; mt < 2; ++mt) {
        int m0 = wm * 32 + mt * 16 + (lane >> 2);
        #pragma unroll
        for (int h = 0; h < 2; ++h) {
            int m = m0 + h * 8;
            if (m >= NI) continue;
            size_t rowoff = (size_t)(b * NI + m) * OBJ;
            #pragma unroll
            for (int nt = 0; nt < 8; ++nt) {
                int col = ncol + wn * 64 + nt * 8 + (lane & 3) * 2;
                *reinterpret_cast<__half2*>(T + rowoff + col) =
                    __floats2half2_rn(acc[mt][nt][h * 2 + 0], acc[mt][nt][h * 2 + 1]);
            }
        }
    }
}

// ================ fp16 GEMM 128x128 (s_proj; handles K tails) =================
__global__ __launch_bounds__(256, 2) void gemm_mma_h(
    const __half* __restrict__ A, const __half* __restrict__ Bm,
    const float* __restrict__ scale, const float* __restrict__ bias,
    __half* __restrict__ C,
    int K, int lda, int ldb, int ldc)
{
    extern __shared__ __align__(128) char dynsmem[];
    const uint32_t sbase = smem_u32(dynsmem);
    const int tid  = threadIdx.x;
    const int lane = tid & 31;
    const int wid  = tid >> 5;
    const int wm   = wid >> 2;
    const int wn   = wid & 3;
    const int rowBase = blockIdx.y * 128;
    const int colBase = blockIdx.x * 128;

    const __half* Ablk = A  + (size_t)rowBase * lda;
    const __half* Bblk = Bm + (size_t)colBase * ldb;
    const int KT = (K + 63) / 64;

    auto load_chunk = [&](int L) {
        const int s = L % NST;
        const int k0 = L * 64;
        const uint32_t stage = sbase + s * STAGE_BYTES;
        const bool tail = (k0 + 64 > K);
        #pragma unroll
        for (int it = 0; it < 8; ++it) {
            int t = tid + it * 256;
            int which = t >> 10;
            int r = (t >> 3) & 127;
            int j = t & 7;
            int gk = k0 + j * 8;
            const __half* src = (which ? Bblk + (size_t)r * ldb
                                       : Ablk + (size_t)r * lda) + gk;
            uint32_t dst = stage + which * 16384 + r * 128 + ((j ^ (r & 7)) << 4);
            if (!tail) {
                asm volatile("cp.async.cg.shared.global [%0], [%1], 16;"
                             :: "r"(dst), "l"(src) : "memory");
            } else {
                uint32_t w[4];
                #pragma unroll
                for (int u = 0; u < 4; ++u) {
                    __half lo = (gk + 2 * u     < K) ? src[2 * u]     : __half(0.f);
                    __half hi = (gk + 2 * u + 1 < K) ? src[2 * u + 1] : __half(0.f);
                    __half2 h2 = __halves2half2(lo, hi);
                    w[u] = *reinterpret_cast<uint32_t*>(&h2);
                }
                asm volatile("st.shared.v4.b32 [%0], {%1,%2,%3,%4};"
                             :: "r"(dst), "r"(w[0]), "r"(w[1]), "r"(w[2]), "r"(w[3])
                             : "memory");
            }
        }
    };

    #pragma unroll
    for (int p = 0; p < NST - 1; ++p) {
        if (p < KT) load_chunk(p);
        asm volatile("cp.async.commit_group;" ::: "memory");
    }

    float acc[4][4][4];
    #pragma unroll
    for (int a = 0; a < 4; a++)
        #pragma unroll
        for (int b = 0; b < 4; b++)
            #pragma unroll
            for (int c = 0; c < 4; c++) acc[a][b][c] = 0.f;

    for (int c = 0; c < KT; ++c) {
        asm volatile("cp.async.wait_group 1;" ::: "memory");
        __syncthreads();

        const int L = c + NST - 1;
        if (L < KT) load_chunk(L);
        asm volatile("cp.async.commit_group;" ::: "memory");

        const uint32_t ast = sbase + (c % NST) * STAGE_BYTES;
        const uint32_t bst = ast + 16384;

        #pragma unroll
        for (int ks = 0; ks < 4; ++ks) {
            uint32_t af[4][4], bf[4][2];
            #pragma unroll
            for (int mt = 0; mt < 4; ++mt) {
                int r = wm * 64 + mt * 16 + (lane & 15);
                int ch = ks * 2 + (lane >> 4);
                uint32_t addr = ast + r * 128 + ((ch ^ (r & 7)) << 4);
                asm volatile("ldmatrix.sync.aligned.m8n8.x4.shared.b16 "
                             "{%0,%1,%2,%3}, [%4];"
                             : "=r"(af[mt][0]), "=r"(af[mt][1]),
                               "=r"(af[mt][2]), "=r"(af[mt][3])
                             : "r"(addr));
            }
            #pragma unroll
            for (int np = 0; np < 2; ++np) {
                int tile = np * 2 + (lane >> 4);
                int half_k = (lane >> 3) & 1;
                int r = wn * 32 + tile * 8 + (lane & 7);
                int ch = ks * 2 + half_k;
                uint32_t addr = bst + r * 128 + ((ch ^ (r & 7)) << 4);
                asm volatile("ldmatrix.sync.aligned.m8n8.x4.shared.b16 "
                             "{%0,%1,%2,%3}, [%4];"
                             : "=r"(bf[np * 2][0]), "=r"(bf[np * 2][1]),
                               "=r"(bf[np * 2 + 1][0]), "=r"(bf[np * 2 + 1][1])
                             : "r"(addr));
            }
            #pragma unroll
            for (int mt = 0; mt < 4; ++mt)
                #pragma unroll
                for (int nt = 0; nt < 4; ++nt) {
                    asm volatile(
                        "mma.sync.aligned.m16n8k16.row.col.f32.f16.f16.f32 "
                        "{%0,%1,%2,%3}, {%4,%5,%6,%7}, {%8,%9}, {%0,%1,%2,%3};"
                        : "+f"(acc[mt][nt][0]), "+f"(acc[mt][nt][1]),
                          "+f"(acc[mt][nt][2]), "+f"(acc[mt][nt][3])
                        : "r"(af[mt][0]), "r"(af[mt][1]),
                          "r"(af[mt][2]), "r"(af[mt][3]),
                          "r"(bf[nt][0]), "r"(bf[nt][1]));
                }
        }
    }

    #pragma unroll
    for (int mt = 0; mt < 4; ++mt) {
        int r0 = rowBase + wm * 64 + mt * 16 + (lane >> 2);
        #pragma unroll
        for (int nt = 0; nt < 4; ++nt) {
            int col = colBase + wn * 32 + nt * 8 + (lane & 3) * 2;
            float2 sc = *reinterpret_cast<const float2*>(scale + col);
            float2 bi = *reinterpret_cast<const float2*>(bias + col);
            #pragma unroll
            for (int h = 0; h < 2; ++h) {
                int row = r0 + h * 8;
                float ox = fmaxf(acc[mt][nt][h * 2 + 0] * sc.x + bi.x, 0.f);
                float oy = fmaxf(acc[mt][nt][h * 2 + 1] * sc.y + bi.y, 0.f);
                *reinterpret_cast<__half2*>(C + (size_t)row * ldc + col) =
                    __floats2half2_rn(ox, oy);
            }
        }
    }
}

// ====== fp16 GEMM 256x128, 4-stage, continuous frag pipeline ==================
// MODE 0: C(half)  = relu(acc*scale+bias)
// MODE 2: C(half)  = acc (raw)
// MODE 3: C(float) = resid + relu(scale*(acc + T) + bias)
template<int MODE>
__global__ __launch_bounds__(256, 1) void gemm_mma_h2(
    const __half* __restrict__ A, const __half* __restrict__ Bm,
    const float* __restrict__ scale, const float* __restrict__ bias,
    const float* __restrict__ resid, const __half* __restrict__ Tadd,
    void* __restrict__ Cv,
    int K, int lda, int ldb, int ldc)
{
    extern __shared__ __align__(128) char dynsmem[];
    const uint32_t sbase = smem_u32(dynsmem);
    const int tid  = threadIdx.x;
    const int lane = tid & 31;
    const int wid  = tid >> 5;
    const int wm   = wid >> 1;
    const int wn   = wid & 1;
    const int rowBase = blockIdx.y * 256;
    const int colBase = blockIdx.x * 128;

    const __half* Ablk = A  + (size_t)rowBase * lda;
    const __half* Bblk = Bm + (size_t)colBase * ldb;
    const int KT = K / 64;

    const int rA = wm * 64 + (lane & 15);
    const int rB = wn * 64 + (lane & 7);
    const int chA_half = (lane >> 4);
    const int tB_base  = (lane >> 4);
    const int chB_half = (lane >> 3) & 1;

    auto load_chunk = [&](int L) {
        const int s = L % NST2;
        const int k0 = L * 64;
        const uint32_t stage = sbase + s * STAGE2_BYTES;
        #pragma unroll
        for (int it = 0; it < 12; ++it) {
            int t = tid + it * 256;
            bool isB = t >= 2048;
            int tt = isB ? t - 2048 : t;
            int r = tt >> 3;
            int j = tt & 7;
            int gk = k0 + j * 8;
            const __half* src = (isB ? Bblk + (size_t)r * ldb
                                     : Ablk + (size_t)r * lda) + gk;
            uint32_t dst = stage + (isB ? 32768 : 0) + r * 128 + ((j ^ (r & 7)) << 4);
            asm volatile("cp.async.cg.shared.global [%0], [%1], 16;"
                         :: "r"(dst), "l"(src) : "memory");
        }
    };

    uint32_t af[2][4][4], bf[2][8][2];

    auto load_frags = [&](uint32_t ast, uint32_t bst, int ks, int pb) {
        #pragma unroll
        for (int mt = 0; mt < 4; ++mt) {
            int r = rA + mt * 16;
            int ch = ks * 2 + chA_half;
            uint32_t addr = ast + r * 128 + ((ch ^ (r & 7)) << 4);
            asm volatile("ldmatrix.sync.aligned.m8n8.x4.shared.b16 "
                         "{%0,%1,%2,%3}, [%4];"
                         : "=r"(af[pb][mt][0]), "=r"(af[pb][mt][1]),
                           "=r"(af[pb][mt][2]), "=r"(af[pb][mt][3])
                         : "r"(addr));
        }
        #pragma unroll
        for (int np = 0; np < 4; ++np) {
            int tile = np * 2 + tB_base;
            int r = rB + tile * 8;
            int ch = ks * 2 + chB_half;
            uint32_t addr = bst + r * 128 + ((ch ^ (r & 7)) << 4);
            asm volatile("ldmatrix.sync.aligned.m8n8.x4.shared.b16 "
                         "{%0,%1,%2,%3}, [%4];"
                         : "=r"(bf[pb][np * 2][0]), "=r"(bf[pb][np * 2][1]),
                           "=r"(bf[pb][np * 2 + 1][0]), "=r"(bf[pb][np * 2 + 1][1])
                         : "r"(addr));
        }
    };

    #pragma unroll
    for (int p = 0; p < NST2 - 1; ++p) {
        load_chunk(p);
        asm volatile("cp.async.commit_group;" ::: "memory");
    }
    asm volatile("cp.async.wait_group 2;" ::: "memory");
    __syncthreads();
    load_frags(sbase, sbase + 32768, 0, 0);

    float acc[4][8][4];
    #pragma unroll
    for (int a = 0; a < 4; a++)
        #pragma unroll
        for (int b = 0; b < 8; b++)
            #pragma unroll
            for (int c = 0; c < 4; c++) acc[a][b][c] = 0.f;

    for (int c = 0; c < KT; ++c) {
        asm volatile("cp.async.wait_group 1;" ::: "memory");
        __syncthreads();

        const uint32_t ast  = sbase + (c % NST2) * STAGE2_BYTES;
        const uint32_t bst  = ast + 32768;
        const uint32_t nast = sbase + ((c + 1) % NST2) * STAGE2_BYTES;
        const uint32_t nbst = nast + 32768;
        const int L = c + NST2 - 1;

        #pragma unroll
        for (int ks = 0; ks < 4; ++ks) {
            if (ks == 1) {
                if (L < KT) load_chunk(L);
                asm volatile("cp.async.commit_group;" ::: "memory");
            }
            if (ks < 3)            load_frags(ast, bst, ks + 1, (ks + 1) & 1);
            else if (c + 1 < KT)   load_frags(nast, nbst, 0, 0);
            const int pb = ks & 1;
            #pragma unroll
            for (int mt = 0; mt < 4; ++mt)
                #pragma unroll
                for (int nt = 0; nt < 8; ++nt) {
                    asm volatile(
                        "mma.sync.aligned.m16n8k16.row.col.f32.f16.f16.f32 "
                        "{%0,%1,%2,%3}, {%4,%5,%6,%7}, {%8,%9}, {%0,%1,%2,%3};"
                        : "+f"(acc[mt][nt][0]), "+f"(acc[mt][nt][1]),
                          "+f"(acc[mt][nt][2]), "+f"(acc[mt][nt][3])
                        : "r"(af[pb][mt][0]), "r"(af[pb][mt][1]),
                          "r"(af[pb][mt][2]), "r"(af[pb][mt][3]),
                          "r"(bf[pb][nt][0]), "r"(bf[pb][nt][1]));
                }
        }
    }

    #pragma unroll
    for (int mt = 0; mt < 4; ++mt) {
        int r0 = rowBase + wm * 64 + mt * 16 + (lane >> 2);
        #pragma unroll
        for (int nt = 0; nt < 8; ++nt) {
            int col = colBase + wn * 64 + nt * 8 + (lane & 3) * 2;
            float2 sc, bi;
            if (MODE != 2) {
                sc = *reinterpret_cast<const float2*>(scale + col);
                bi = *reinterpret_cast<const float2*>(bias + col);
            }
            #pragma unroll
            for (int h = 0; h < 2; ++h) {
                int row = r0 + h * 8;
                float ax = acc[mt][nt][h * 2 + 0];
                float ay = acc[mt][nt][h * 2 + 1];
                if (MODE == 2) {
                    __half* C = (__half*)Cv;
                    *reinterpret_cast<__half2*>(C + (size_t)row * ldc + col) =
                        __floats2half2_rn(ax, ay);
                } else if (MODE == 0) {
                    float ox = fmaxf(ax * sc.x + bi.x, 0.f);
                    float oy = fmaxf(ay * sc.y + bi.y, 0.f);
                    __half* C = (__half*)Cv;
                    *reinterpret_cast<__half2*>(C + (size_t)row * ldc + col) =
                        __floats2half2_rn(ox, oy);
                } else {  // MODE 3
                    __half2 th = *reinterpret_cast<const __half2*>(
                        Tadd + (size_t)row * ldc + col);
                    float2 tf = __half22float2(th);
                    float ox = fmaxf((ax + tf.x) * sc.x + bi.x, 0.f);
                    float oy = fmaxf((ay + tf.y) * sc.y + bi.y, 0.f);
                    float2 rr = *reinterpret_cast<const float2*>(
                        resid + (size_t)row * ldc + col);
                    float2 o = {ox + rr.x, oy + rr.y};
                    float* C = (float*)Cv;
                    *reinterpret_cast<float2*>(C + (size_t)row * ldc + col) = o;
                }
            }
        }
    }
}

// ---------------------------------------------------------------------------
extern "C" void kernel_launch(void* const* d_in, const int* in_sizes, int n_in,
                              void* d_out, int out_size)
{
    const float* i_in   = (const float*)d_in[0];
    const float* s_in   = (const float*)d_in[1];
    const float* pi_in  = (const float*)d_in[2];
    const float* ps_in  = (const float*)d_in[3];
    const int*   mask_s = (const int*)  d_in[4];
    const float* vi = (const float*)d_in[5];
    const float* gi = (const float*)d_in[6];
    const float* bi = (const float*)d_in[7];
    const float* vs = (const float*)d_in[8];
    const float* gs = (const float*)d_in[9];
    const float* bs = (const float*)d_in[10];
    const float* vc = (const float*)d_in[11];
    const float* gc = (const float*)d_in[12];
    const float* bc = (const float*)d_in[13];
    float* out = (float*)d_out;

    float *si_p, *ss_p, *sc_p;
    __half *att16_p, *sproj_p, *sWT_p, *T_p, *iproj_p;
    __half *i16_p, *s16_p, *vi16_p, *vs16_p, *vc16_p;
    cudaGetSymbolAddress((void**)&att16_p, g_att16);
    cudaGetSymbolAddress((void**)&sproj_p, g_sproj);
    cudaGetSymbolAddress((void**)&sWT_p,   g_sWT);
    cudaGetSymbolAddress((void**)&T_p,     g_T);
    cudaGetSymbolAddress((void**)&iproj_p, g_iproj);
    cudaGetSymbolAddress((void**)&si_p,    g_si);
    cudaGetSymbolAddress((void**)&ss_p,    g_ss);
    cudaGetSymbolAddress((void**)&sc_p,    g_sc);
    cudaGetSymbolAddress((void**)&i16_p,   g_i16);
    cudaGetSymbolAddress((void**)&s16_p,   g_s16);
    cudaGetSymbolAddress((void**)&vi16_p,  g_vi16);
    cudaGetSymbolAddress((void**)&vs16_p,  g_vs16);
    cudaGetSymbolAddress((void**)&vc16_p,  g_vc16);

    cudaFuncSetAttribute(gemm_mma_h,     cudaFuncAttributeMaxDynamicSharedMemorySize, SMEM_DYN);
    cudaFuncSetAttribute(gemm_mma_h2<0>, cudaFuncAttributeMaxDynamicSharedMemorySize, SMEM_DYN2);
    cudaFuncSetAttribute(gemm_mma_h2<2>, cudaFuncAttributeMaxDynamicSharedMemorySize, SMEM_DYN2);
    cudaFuncSetAttribute(gemm_mma_h2<3>, cudaFuncAttributeMaxDynamicSharedMemorySize, SMEM_DYN2);

    // Streams + events (created once on the uncaptured correctness call)
    static cudaStream_t s1 = nullptr, s2 = nullptr;
    static cudaEvent_t evRoot = nullptr, evVC = nullptr, evW1 = nullptr;
    static cudaEvent_t evIb = nullptr, evI = nullptr;
    if (s1 == nullptr) {
        cudaStreamCreateWithFlags(&s1, cudaStreamNonBlocking);
        cudaStreamCreateWithFlags(&s2, cudaStreamNonBlocking);
        cudaEventCreateWithFlags(&evRoot, cudaEventDisableTiming);
        cudaEventCreateWithFlags(&evVC,   cudaEventDisableTiming);
        cudaEventCreateWithFlags(&evW1,   cudaEventDisableTiming);
        cudaEventCreateWithFlags(&evIb,   cudaEventDisableTiming);
        cudaEventCreateWithFlags(&evI,    cudaEventDisableTiming);
    }

    constexpr int HALF_ROWS = MI / 2;                  // 6400
    constexpr int HALF_N4   = HALF_ROWS * OBJ / 4;     // 3,276,800

    // ---- fork ------------------------------------------------------------------
    cudaEventRecord(evRoot, 0);
    cudaStreamWaitEvent(s1, evRoot, 0);
    cudaStreamWaitEvent(s2, evRoot, 0);

    // s1: weight converts (vi, vc), then scales si/sc + attention,
    //     then second half of the i conversion (overlaps iproj_a on s2)
    prep_vv_kernel<<<2048, 256, 0, s1>>>(vi, vi16_p, vc, vc16_p);
    cudaEventRecord(evVC, s1);
    prep2b_kernel<<<P2_BLOCKS, 256, 0, s1>>>(vi, gi, si_p, vc, gc, sc_p,
                                             pi_in, ps_in, mask_s, att16_p);
    cudaEventRecord(evW1, s1);
    prep_i_kernel<<<2048, 256, 0, s1>>>(i_in + (size_t)HALF_ROWS * OBJ,
                                        i16_p + (size_t)HALF_ROWS * OBJ, HALF_N4);
    cudaEventRecord(evIb, s1);

    // s2: first half of i conversion, then iproj_a, then iproj_b
    prep_i_kernel<<<2048, 256, 0, s2>>>(i_in, i16_p, HALF_N4);
    cudaStreamWaitEvent(s2, evW1, 0);                 // vi16 + si ready
    gemm_mma_h2<0><<<dim3(PROJ / 128, HALF_ROWS / 256), 256, SMEM_DYN2, s2>>>(
        i16_p, vi16_p, si_p, bi, nullptr, nullptr, iproj_p,
        OBJ, OBJ, OBJ, PROJ);
    cudaStreamWaitEvent(s2, evIb, 0);                 // second half of i16 ready
    gemm_mma_h2<0><<<dim3(PROJ / 128, HALF_ROWS / 256), 256, SMEM_DYN2, s2>>>(
        i16_p + (size_t)HALF_ROWS * OBJ, vi16_p, si_p, bi, nullptr, nullptr,
        iproj_p + (size_t)HALF_ROWS * PROJ,
        OBJ, OBJ, OBJ, PROJ);
    cudaEventRecord(evI, s2);

    // 0: s-side chain
    prep_s_kernel<<<PS_BLOCKS, 256>>>(s_in, s16_p, vs, vs16_p, gs, ss_p);

    gemm_mma_h<<<dim3(PROJ / 128, MS / 128), 256, SMEM_DYN>>>(
        s16_p, vs16_p, ss_p, bs, sproj_p, SEM, SEMP, SEMP, PROJ);

    cudaStreamWaitEvent(0, evVC, 0);
    gemm_mma_h2<2><<<dim3(MS / 128, OBJ / 256), 256, SMEM_DYN2>>>(
        vc16_p + PROJ, sproj_p, nullptr, nullptr, nullptr, nullptr, sWT_p,
        PROJ, 2 * PROJ, PROJ, MS);

    cudaStreamWaitEvent(0, evW1, 0);
    attmm_tc_kernel<<<dim3(OBJ / 128, B_), 256>>>(att16_p, sWT_p, T_p);

    // join: comb needs iproj (s2) + T (0)
    cudaStreamWaitEvent(0, evI, 0);
    gemm_mma_h2<3><<<dim3(OBJ / 128, MI / 256), 256, SMEM_DYN2>>>(
        iproj_p, vc16_p, sc_p, bc, i_in, T_p, out,
        PROJ, PROJ, 2 * PROJ, OBJ);
}